// round 16
// baseline (speedup 1.0000x reference)
#include <cuda_runtime.h>
#include <math.h>
#include <stdint.h>

#define B_   4
#define S_   2048
#define DIN  512
#define U_   64
#define L_OUT 132064

typedef unsigned long long ull;

// ---------------- f32x2 packed helpers (sm_103a) ----------------
__device__ __forceinline__ ull dup2(float x) {
    ull r; asm("mov.b64 %0, {%1, %1};" : "=l"(r) : "f"(x)); return r;
}
__device__ __forceinline__ void fma2(ull &d, ull a, ull b) {
    asm("fma.rn.f32x2 %0, %1, %2, %3;" : "=l"(d) : "l"(a), "l"(b), "l"(d));
}
__device__ __forceinline__ ull mul2(ull a, ull b) {
    ull d; asm("mul.rn.f32x2 %0, %1, %2;" : "=l"(d) : "l"(a), "l"(b)); return d;
}
__device__ __forceinline__ float2 unpk(ull v) {
    float2 f; asm("mov.b64 {%0, %1}, %2;" : "=f"(f.x), "=f"(f.y) : "l"(v)); return f;
}

// ---------------- cp.async helpers ----------------
__device__ __forceinline__ uint32_t smem_u32(const void* p) {
    uint32_t a;
    asm("{ .reg .u64 t; cvta.to.shared.u64 t, %1; cvt.u32.u64 %0, t; }" : "=r"(a) : "l"(p));
    return a;
}
__device__ __forceinline__ void cp16(uint32_t dst, const void* src) {
    asm volatile("cp.async.cg.shared.global [%0], [%1], 16;" :: "r"(dst), "l"(src));
}
__device__ __forceinline__ void cp_commit() {
    asm volatile("cp.async.commit_group;" ::: "memory");
}
__device__ __forceinline__ void cp_wait0() {
    asm volatile("cp.async.wait_group 0;" ::: "memory");
}

// ---------------- scratch ----------------
__device__ float g_Q[B_ * S_ * U_];
__device__ float g_K[B_ * S_ * U_];
__device__ float g_V[B_ * S_ * U_];
__device__ float g_Wt[3 * U_ * DIN];   // W transposed: [p][n][k]

// ======================= Kernel A0: transpose weights (tiny) =======================
__global__ void wt_kernel(const float* __restrict__ Wq,
                          const float* __restrict__ Wk,
                          const float* __restrict__ Wv)
{
    const int p = blockIdx.x;
    const float* W = (p == 0) ? Wq : ((p == 1) ? Wk : Wv);
    float* T = g_Wt + p * U_ * DIN;
    for (int j = threadIdx.x; j < DIN * 16; j += blockDim.x) {
        const int k = j >> 4, f = (j & 15) << 2;
        float4 v = *(const float4*)&W[k * U_ + f];
        T[(f + 0) * DIN + k] = v.x;
        T[(f + 1) * DIN + k] = v.y;
        T[(f + 2) * DIN + k] = v.z;
        T[(f + 3) * DIN + k] = v.w;
    }
}

// ======================= Kernel A: QKV projections (k-packed f32x2) =======================
// Tile M=64 x N=64, 128 threads = 2x2 warps of 32m x 32n.
// Thread (warp wm,wn; lane mg=lane>>3, ngl=lane&7): m = 32wm+mg+4mi (mi<8),
// n = 32wn+ngl+8ni (ni<4). acc2 packs (even k, odd k) partial sums -> both
// operands are LDS.64 k-pairs, no dup2, no A transpose.
// smem: A[64 rows][256B] + B[64 rows][256B], XOR slot swizzle, x2 stages.
#define STG_BYTES 32768
#define PROJ_SMEM 65536

extern __shared__ char prsm[];

__global__ __launch_bounds__(128, 3)
void proj_kernel(const float* __restrict__ query,
                 const float* __restrict__ value,
                 const float* __restrict__ bq,
                 const float* __restrict__ bk,
                 const float* __restrict__ bv)
{
    const int p = blockIdx.y;
    const float* X  = (p == 0) ? query : value;
    const float* Wt = g_Wt + p * U_ * DIN;
    const float* bm = (p == 0) ? bq : ((p == 1) ? bk : bv);
    float* O        = (p == 0) ? g_Q : ((p == 1) ? g_K : g_V);

    const int m0   = blockIdx.x * 64;
    const int tid  = threadIdx.x;
    const int lane = tid & 31;
    const int warp = tid >> 5;
    const int wm   = warp >> 1, wn = warp & 1;
    const int mg   = lane >> 3, ngl = lane & 7;

    const uint32_t sbase = smem_u32(prsm);

    ull acc[8][4];
    #pragma unroll
    for (int i = 0; i < 8; ++i)
        #pragma unroll
        for (int j = 0; j < 4; ++j) acc[i][j] = 0ull;

    // ---- stage loader: 16B cp.async with XOR block swizzle ----
    auto stage_load = [&](int buf, int c) {
        const int k0 = c * 64;
        const uint32_t sA = sbase + (uint32_t)buf * STG_BYTES;
        const uint32_t sB = sA + 16384u;
        #pragma unroll
        for (int it = 0; it < 8; ++it) {
            const int j = tid + it * 128;
            const int m = j >> 4, f = j & 15;
            cp16(sA + (uint32_t)(m * 256 + 16 * (f ^ (m & 3))),
                 &X[(size_t)(m0 + m) * DIN + k0 + 4 * f]);
        }
        #pragma unroll
        for (int it = 0; it < 8; ++it) {
            const int j = tid + it * 128;
            const int n = j >> 4, f = j & 15;
            cp16(sB + (uint32_t)(n * 256 + 16 * (f ^ (n & 7))),
                 &Wt[(size_t)n * DIN + k0 + 4 * f]);
        }
        cp_commit();
    };

    stage_load(0, 0);

    for (int c = 0; c < 8; ++c) {
        cp_wait0();
        __syncthreads();
        if (c + 1 < 8) stage_load((c + 1) & 1, c + 1);

        const char* Ab = prsm + (c & 1) * STG_BYTES + (32 * wm + mg) * 256;
        const char* Bb = prsm + (c & 1) * STG_BYTES + 16384 + (32 * wn + ngl) * 256;

        for (int p8 = 0; p8 < 32; p8 += 8) {
            #pragma unroll
            for (int pp = 0; pp < 8; ++pp) {
                const int kp = p8 + pp;
                const uint32_t oA = (uint32_t)(((kp >> 1) ^ mg)  << 4) | ((kp & 1) << 3);
                const uint32_t oB = (uint32_t)(((kp >> 1) ^ ngl) << 4) | ((kp & 1) << 3);
                const char* bptr = Bb + oB;
                ull b0 = *(const ull*)(bptr);
                ull b1 = *(const ull*)(bptr + 2048);
                ull b2 = *(const ull*)(bptr + 4096);
                ull b3 = *(const ull*)(bptr + 6144);
                const char* aptr = Ab + oA;
                #pragma unroll
                for (int mi = 0; mi < 8; ++mi) {
                    ull a = *(const ull*)(aptr + mi * 1024);
                    fma2(acc[mi][0], a, b0);
                    fma2(acc[mi][1], a, b1);
                    fma2(acc[mi][2], a, b2);
                    fma2(acc[mi][3], a, b3);
                }
            }
        }
        __syncthreads();
    }

    // epilogue: reduce pair, add bias, store
    float bb[4];
    #pragma unroll
    for (int ni = 0; ni < 4; ++ni) bb[ni] = bm[32 * wn + ngl + 8 * ni];
    #pragma unroll
    for (int mi = 0; mi < 8; ++mi) {
        const int m = m0 + 32 * wm + mg + 4 * mi;
        float* orow = O + (size_t)m * U_;
        #pragma unroll
        for (int ni = 0; ni < 4; ++ni) {
            float2 e = unpk(acc[mi][ni]);
            orow[32 * wn + ngl + 8 * ni] = e.x + e.y + bb[ni];
        }
    }
}

// ======================= Kernel B: banded attention (R14 verbatim, ~41.5us) =======================
#define TJ   32
#define NBK  160
#define NBV  162
#define KP   68

__device__ __forceinline__ int off_of(int s)
{
    if (s <= 32)   return s * 33 + (s * (s - 1)) / 2;
    if (s <= 2016) return 1552 + (s - 32) * 65;
    return 130512 + ((2145 - s) * (s - 2016)) / 2;
}

extern __shared__ float sm_b[];

__global__ __launch_bounds__(512, 2)
void attn_kernel(float* __restrict__ out)
{
    float* Ks = sm_b;
    float* Vs = Ks + NBK * KP;
    float* Qs = Vs + NBV * 64;
    float* Es = Qs + TJ * 64;

    const int b     = blockIdx.y;
    const int j0    = blockIdx.x * TJ;
    const int tid   = threadIdx.x;
    const int ubase = j0 - 64;

    {
        const size_t gbase = (size_t)b * S_ * U_;
        for (int i = tid; i < TJ * 16; i += 512)
            *(float4*)&Qs[i * 4] = *(const float4*)&g_Q[gbase + (size_t)j0 * U_ + i * 4];
        for (int i = tid; i < NBK * 16; i += 512) {
            const int ug = i >> 4, d4 = (i & 15) << 2;
            int u = ubase + ug;
            u = (u < 0) ? 0 : ((u > S_ - 1) ? S_ - 1 : u);
            *(float4*)&Ks[ug * KP + d4] = *(const float4*)&g_K[gbase + (size_t)u * U_ + d4];
            *(float4*)&Vs[ug * 64 + d4] = *(const float4*)&g_V[gbase + (size_t)u * U_ + d4];
        }
        for (int i = tid; i < 2 * 16; i += 512) {
            const int ug = 160 + (i >> 4), d4 = (i & 15) << 2;
            *(float4*)&Vs[ug * 64 + d4] = make_float4(0.f, 0.f, 0.f, 0.f);
        }
        for (int i = tid; i < TJ * 132 / 4; i += 512)
            *(float4*)&Es[i * 4] = make_float4(0.f, 0.f, 0.f, 0.f);
    }
    __syncthreads();

    const int w    = tid >> 5;
    const int lane = tid & 31;
    const int jg   = lane >> 4;
    const int ul   = lane & 15;
    const int j_a  = j0 + 2 * w;
    const int jme  = j_a + jg;

    {
        float acc[9];
        int rowoff[9];
        #pragma unroll
        for (int t = 0; t < 9; ++t) {
            acc[t] = 0.f;
            int r = ul + 16 * t; if (r > 129) r = 129;
            rowoff[t] = (2 * w + r) * KP;
        }
        const float* qp = Qs + (2 * w + jg) * 64;
        #pragma unroll 4
        for (int d4 = 0; d4 < 64; d4 += 4) {
            float4 q = *(const float4*)&qp[d4];
            #pragma unroll
            for (int t = 0; t < 9; ++t) {
                float4 kf = *(const float4*)&Ks[rowoff[t] + d4];
                acc[t] += q.x * kf.x + q.y * kf.y + q.z * kf.z + q.w * kf.w;
            }
        }
        const float NEG_INF = __int_as_float(0xff800000);
        float sc[9], m = NEG_INF;
        #pragma unroll
        for (int t = 0; t < 9; ++t) {
            const int r  = ul + 16 * t;
            const int uu = r - jg;
            const int u  = ubase + 2 * w + r;
            const bool valid = (uu >= 0) && (uu <= 128) && (u >= 0) && (u < S_);
            sc[t] = valid ? acc[t] * 0.125f : NEG_INF;
            m = fmaxf(m, sc[t]);
        }
        #pragma unroll
        for (int off = 8; off > 0; off >>= 1)
            m = fmaxf(m, __shfl_xor_sync(0xffffffffu, m, off));
        float* erow = Es + (2 * w + jg) * 132;
        #pragma unroll
        for (int t = 0; t < 9; ++t) {
            const int uu = ul + 16 * t - jg;
            if (uu >= 0 && uu <= 128)
                erow[uu] = __expf(sc[t] - m);
        }
    }
    __syncthreads();

    {
        const int dl = lane & 15;
        const int smin_u = (j_a - 32 > 0) ? (j_a - 32) : 0;
        const int smax_u = (j_a + 33 < S_ - 1) ? (j_a + 33) : (S_ - 1);
        const int slo = (jme - 32 > 0) ? (jme - 32) : 0;
        const int shi = (jme + 32 < S_ - 1) ? (jme + 32) : (S_ - 1);

        const float* ej = Es + (2 * w + jg) * 132 + 64 - jme;
        float Dv = 0.f; ull n0 = 0ull, n1 = 0ull;
        {
            const int ulo = (smin_u - 32 > 0) ? (smin_u - 32) : 0;
            const int uhi = (smin_u + 33 < S_) ? (smin_u + 33) : S_;
            const float* pe = ej + ulo;
            const float* pv = Vs + (ulo - ubase) * 64 + dl * 4;
            for (int u = ulo; u < uhi; ++u) {
                const float e = *pe++;
                const ulonglong2 v = *(const ulonglong2*)pv; pv += 64;
                const ull ed = dup2(e);
                fma2(n0, ed, v.x); fma2(n1, ed, v.y);
                Dv += e;
            }
        }

        const int start0 = (smin_u - 32 > 0) ? (smin_u - 32) : 0;
        float* po = out + (size_t)b * L_OUT * U_
                        + ((size_t)off_of(smin_u) + (jme - start0)) * U_ + dl * 4;
        const float* pea = ej + smin_u + 33;
        const float* pes = ej + smin_u - 32;
        const float* pva = Vs + (smin_u + 33 - ubase) * 64 + dl * 4;
        const float* pvs = Vs + (smin_u - 32 - ubase) * 64 + dl * 4;

        for (int s = smin_u; s <= smax_u; ++s) {
            if (s >= slo && s <= shi) {
                const float invD = __fdividef(1.f, Dv);
                const ull dd = dup2(invD);
                ulonglong2 o; o.x = mul2(n0, dd); o.y = mul2(n1, dd);
                *(ulonglong2*)po = o;
            }
            int delta = s + 33; if (delta > 64) delta = 64;
            int d2 = 2079 - s;  if (d2 < delta) delta = d2;
            po += (size_t)delta * U_;

            const float ea = *pea++;
            const float es = *pes++;
            const ulonglong2 va = *(const ulonglong2*)pva; pva += 64;
            const ulonglong2 vv = *(const ulonglong2*)pvs; pvs += 64;
            const ull ead = dup2(ea);
            fma2(n0, ead, va.x); fma2(n1, ead, va.y);
            const ull esd = dup2(-es);
            fma2(n0, esd, vv.x); fma2(n1, esd, vv.y);
            Dv += (ea - es);
        }
    }
}

// ======================= launch =======================
extern "C" void kernel_launch(void* const* d_in, const int* in_sizes, int n_in,
                              void* d_out, int out_size)
{
    const float* query = (const float*)d_in[0];
    const float* value = (const float*)d_in[1];
    const float* Wq    = (const float*)d_in[2];
    const float* bq    = (const float*)d_in[3];
    const float* Wk    = (const float*)d_in[4];
    const float* bk    = (const float*)d_in[5];
    const float* Wv    = (const float*)d_in[6];
    const float* bv    = (const float*)d_in[7];
    float* out = (float*)d_out;

    wt_kernel<<<3, 256>>>(Wq, Wk, Wv);

    cudaFuncSetAttribute(proj_kernel, cudaFuncAttributeMaxDynamicSharedMemorySize, PROJ_SMEM);
    dim3 gA(8192 / 64, 3);
    proj_kernel<<<gA, 128, PROJ_SMEM>>>(query, value, bq, bk, bv);

    const int smem_bytes = (NBK * KP + NBV * 64 + TJ * 64 + TJ * 132) * (int)sizeof(float);
    cudaFuncSetAttribute(attn_kernel, cudaFuncAttributeMaxDynamicSharedMemorySize, smem_bytes);
    dim3 gB(S_ / TJ, B_);
    attn_kernel<<<gB, 512, smem_bytes>>>(out);
}